// round 4
// baseline (speedup 1.0000x reference)
#include <cuda_runtime.h>

// ---------------------------------------------------------------------------
// PPN on 3-level sparse voxel grid — f32x2 packed-FMA convs, <48KB smem,
// plain padded smem rows (swizzle removed: it overlapped on phase wrap).
// output: points [N3,10] | ppn1 [N1,6] | ppn2 [N2,6] | mask1 [N1] | mask2 [N2]
// ---------------------------------------------------------------------------

#define N1_MAX 65536
#define N2_MAX 262144
#define N3_MAX 262144

__device__ float g_y1[(size_t)N1_MAX * 80];
__device__ float g_f2m[(size_t)N2_MAX * 48];
__device__ float g_y2[(size_t)N2_MAX * 48];
__device__ float g_f3m[(size_t)N3_MAX * 16];
__device__ float g_z[(size_t)N3_MAX * 16];

typedef unsigned long long ull;

__device__ __forceinline__ ull pk2(float x, float y) {
    ull r; asm("mov.b64 %0, {%1, %2};" : "=l"(r) : "f"(x), "f"(y)); return r;
}
__device__ __forceinline__ void fma2(ull& d, ull a, ull b) {
    asm("fma.rn.f32x2 %0, %1, %2, %0;" : "+l"(d) : "l"(a), "l"(b));
}
__device__ __forceinline__ float2 up2(ull v) {
    float a, b; asm("mov.b64 {%0, %1}, %2;" : "=f"(a), "=f"(b) : "l"(v));
    return make_float2(a, b);
}

// ---------------------------------------------------------------------------
// Submanifold conv via f32x2, CIN staged in chunks of CCH columns.
// out[n,d] = sum_k sum_c feat[nbr[n,k],c] * W[k,c,d]
// ---------------------------------------------------------------------------
template <int CIN, int COUT, int TN, int RN, int RD, int NTX, int CCH>
__global__ __launch_bounds__(128)
void subconv2(const float* __restrict__ feat, const int* __restrict__ nbr,
              const float* __restrict__ W, float* __restrict__ out, int N) {
    constexpr int CP = CCH + 4;
    constexpr int NTY = TN / RN;
    constexpr int NTH = NTX * NTY;
    static_assert(NTH == 128, "128 threads");
    static_assert(CIN % CCH == 0 && CCH % 4 == 0 && RD % 4 == 0, "");
    constexpr int NH = CIN / CCH;
    constexpr int VEC = CCH / 4;
    constexpr int NP = RD / 2;
    constexpr int NU = RD / 4;

    extern __shared__ float sh[];
    float* sW = sh;                        // [CCH][COUT] natural layout
    float* sF = sh + CCH * COUT;           // [TN][CP] padded rows
    __shared__ int sIdx[TN];

    const int tid = threadIdx.x;
    const int tx = tid % NTX, ty = tid / NTX;
    const int n0 = blockIdx.x * TN;
    const int nb = ty * RN, db = tx * RD;

    ull acc[RN][NP];
#pragma unroll
    for (int i = 0; i < RN; ++i)
#pragma unroll
        for (int p = 0; p < NP; ++p) acc[i][p] = 0ULL;

    for (int k = 0; k < 27; ++k) {
        for (int i = tid; i < TN; i += NTH) {
            int n = n0 + i;
            sIdx[i] = (n < N) ? nbr[n * 27 + k] : N;
        }
        const float* Wk = W + k * CIN * COUT;
#pragma unroll
        for (int h = 0; h < NH; ++h) {
            __syncthreads();   // protect sW/sF reuse; orders sIdx for h==0
            for (int i = tid; i < CCH * COUT; i += NTH)
                sW[i] = Wk[h * CCH * COUT + i];
            const int bc = h * CCH;
            for (int i = tid; i < TN * VEC; i += NTH) {
                int n = i / VEC, c4 = (i - n * VEC) * 4;
                int idx = sIdx[n];
                float4 v = make_float4(0.f, 0.f, 0.f, 0.f);
                if ((unsigned)idx < (unsigned)N)
                    v = *reinterpret_cast<const float4*>(
                        feat + (size_t)idx * CIN + bc + c4);
                *reinterpret_cast<float4*>(sF + n * CP + c4) = v;
            }
            __syncthreads();

#pragma unroll
            for (int c4 = 0; c4 < CCH; c4 += 4) {
                float4 A[RN];
#pragma unroll
                for (int i = 0; i < RN; ++i)
                    A[i] = *reinterpret_cast<const float4*>(
                        sF + (nb + i) * CP + c4);
#pragma unroll
                for (int cc = 0; cc < 4; ++cc) {
                    ull as[RN];
#pragma unroll
                    for (int i = 0; i < RN; ++i) {
                        float v = (cc == 0) ? A[i].x : (cc == 1) ? A[i].y
                                 : (cc == 2) ? A[i].z : A[i].w;
                        as[i] = pk2(v, v);
                    }
                    const float* wrow = sW + (c4 + cc) * COUT + db;
#pragma unroll
                    for (int u = 0; u < NU; ++u) {
                        float4 B = *reinterpret_cast<const float4*>(wrow + 4 * u);
                        ull b0 = pk2(B.x, B.y), b1 = pk2(B.z, B.w);
#pragma unroll
                        for (int i = 0; i < RN; ++i) {
                            fma2(acc[i][2 * u], as[i], b0);
                            fma2(acc[i][2 * u + 1], as[i], b1);
                        }
                    }
                }
            }
        }
    }

#pragma unroll
    for (int i = 0; i < RN; ++i) {
        int n = n0 + nb + i;
        if (n < N) {
#pragma unroll
            for (int u = 0; u < NU; ++u) {
                float2 p0 = up2(acc[i][2 * u]), p1 = up2(acc[i][2 * u + 1]);
                float4 o = make_float4(p0.x, p0.y, p1.x, p1.y);
                *reinterpret_cast<float4*>(out + (size_t)n * COUT + db + 4 * u) = o;
            }
        }
    }
}

// ---------------------------------------------------------------------------
// Score head (Cout=2) + ppn concat + softmax-threshold mask (R1-proven form).
// softmax([s0,s1])[1] > 0.8  <=>  1/(1+exp(s0-s1)) > 0.8
// ---------------------------------------------------------------------------
template <int CIN>
__global__ void score_ppn_mask(const float* __restrict__ feat,
                               const int* __restrict__ nbr,
                               const float* __restrict__ Ws,
                               const int* __restrict__ coords,
                               float* __restrict__ ppn,
                               float* __restrict__ mask, int N) {
    __shared__ float sW[27 * 2 * CIN];  // [k][d][c]
    for (int i = threadIdx.x; i < 27 * CIN * 2; i += blockDim.x) {
        int k = i / (CIN * 2);
        int r = i - k * CIN * 2;
        int c = r >> 1, d = r & 1;
        sW[(k * 2 + d) * CIN + c] = Ws[i];
    }
    __syncthreads();
    int n = blockIdx.x * blockDim.x + threadIdx.x;
    if (n >= N) return;

    float a0 = 0.f, a1 = 0.f;
    for (int k = 0; k < 27; ++k) {
        int idx = nbr[n * 27 + k];
        if ((unsigned)idx < (unsigned)N) {
            const float4* fr = reinterpret_cast<const float4*>(feat + (size_t)idx * CIN);
            const float4* w0 = reinterpret_cast<const float4*>(sW + (k * 2 + 0) * CIN);
            const float4* w1 = reinterpret_cast<const float4*>(sW + (k * 2 + 1) * CIN);
#pragma unroll
            for (int j = 0; j < CIN / 4; ++j) {
                float4 v = fr[j], x = w0[j], y = w1[j];
                a0 += v.x * x.x + v.y * x.y + v.z * x.z + v.w * x.w;
                a1 += v.x * y.x + v.y * y.y + v.z * y.z + v.w * y.w;
            }
        }
    }
    ppn[(size_t)n * 6 + 0] = (float)coords[n * 4 + 0];
    ppn[(size_t)n * 6 + 1] = (float)coords[n * 4 + 1];
    ppn[(size_t)n * 6 + 2] = (float)coords[n * 4 + 2];
    ppn[(size_t)n * 6 + 3] = (float)coords[n * 4 + 3];
    ppn[(size_t)n * 6 + 4] = a0;
    ppn[(size_t)n * 6 + 5] = a1;
    float p = 1.f / (1.f + expf(a0 - a1));
    mask[n] = (p > 0.8f) ? 1.f : 0.f;
}

// featm[j,:] = feat[j,:] * mask[parent[j]]
template <int C>
__global__ void apply_att(const float* __restrict__ feat,
                          const int* __restrict__ parent,
                          const float* __restrict__ mask,
                          float* __restrict__ outF, int N) {
    int i = blockIdx.x * blockDim.x + threadIdx.x;
    int total = N * (C / 4);
    if (i >= total) return;
    int n = i / (C / 4);
    float m = mask[parent[n]];
    float4 v = reinterpret_cast<const float4*>(feat)[i];
    v.x *= m; v.y *= m; v.z *= m; v.w *= m;
    reinterpret_cast<float4*>(outF)[i] = v;
}

// Fine heads fused (R1-proven form): points[n, 0:3|3:5|5:10].
__global__ void heads_kernel(const float* __restrict__ z,
                             const int* __restrict__ nbr,
                             const float* __restrict__ Wp,
                             const float* __restrict__ Wsc,
                             const float* __restrict__ Wt,
                             float* __restrict__ points, int N) {
    __shared__ float sW[27 * 10 * 16];  // [k][d][c]
    for (int i = threadIdx.x; i < 27 * 16 * 3; i += blockDim.x) {
        int k = i / 48; int r = i - k * 48; int c = r / 3; int d = r - c * 3;
        sW[(k * 10 + d) * 16 + c] = Wp[i];
    }
    for (int i = threadIdx.x; i < 27 * 16 * 2; i += blockDim.x) {
        int k = i / 32; int r = i - k * 32; int c = r >> 1; int d = r & 1;
        sW[(k * 10 + 3 + d) * 16 + c] = Wsc[i];
    }
    for (int i = threadIdx.x; i < 27 * 16 * 5; i += blockDim.x) {
        int k = i / 80; int r = i - k * 80; int c = r / 5; int d = r - c * 5;
        sW[(k * 10 + 5 + d) * 16 + c] = Wt[i];
    }
    __syncthreads();
    int n = blockIdx.x * blockDim.x + threadIdx.x;
    if (n >= N) return;

    float acc[10];
#pragma unroll
    for (int d = 0; d < 10; ++d) acc[d] = 0.f;

    for (int k = 0; k < 27; ++k) {
        int idx = nbr[n * 27 + k];
        if ((unsigned)idx < (unsigned)N) {
            const float4* zr = reinterpret_cast<const float4*>(z + (size_t)idx * 16);
            float4 v0 = zr[0], v1 = zr[1], v2 = zr[2], v3 = zr[3];
#pragma unroll
            for (int d = 0; d < 10; ++d) {
                const float4* wr = reinterpret_cast<const float4*>(sW + (k * 10 + d) * 16);
                float4 w0 = wr[0], w1 = wr[1], w2 = wr[2], w3 = wr[3];
                acc[d] += v0.x * w0.x + v0.y * w0.y + v0.z * w0.z + v0.w * w0.w
                        + v1.x * w1.x + v1.y * w1.y + v1.z * w1.z + v1.w * w1.w
                        + v2.x * w2.x + v2.y * w2.y + v2.z * w2.z + v2.w * w2.w
                        + v3.x * w3.x + v3.y * w3.y + v3.z * w3.z + v3.w * w3.w;
            }
        }
    }
#pragma unroll
    for (int d = 0; d < 10; ++d) points[(size_t)n * 10 + d] = acc[d];
}

// ---------------------------------------------------------------------------
static constexpr int smem_sub(int CCH, int COUT, int TN) {
    return (CCH * COUT + TN * (CCH + 4) + 32) * (int)sizeof(float);
}

extern "C" void kernel_launch(void* const* d_in, const int* in_sizes, int n_in,
                              void* d_out, int out_size) {
    const float* feat1 = (const float*)d_in[0];
    const float* feat2 = (const float*)d_in[1];
    const float* feat3 = (const float*)d_in[2];
    const float* W1  = (const float*)d_in[3];
    const float* W1s = (const float*)d_in[4];
    const float* W2  = (const float*)d_in[5];
    const float* W2s = (const float*)d_in[6];
    const float* W3  = (const float*)d_in[7];
    const float* W3p = (const float*)d_in[8];
    const float* W3s = (const float*)d_in[9];
    const float* W3t = (const float*)d_in[10];
    const int* nbr1 = (const int*)d_in[11];
    const int* nbr2 = (const int*)d_in[12];
    const int* nbr3 = (const int*)d_in[13];
    const int* parent2 = (const int*)d_in[14];
    const int* parent3 = (const int*)d_in[15];
    const int* coords1 = (const int*)d_in[16];
    const int* coords2 = (const int*)d_in[17];

    const int N1 = in_sizes[0] / 80;
    const int N2 = in_sizes[1] / 48;
    const int N3 = in_sizes[2] / 16;

    float* out = (float*)d_out;
    float* points = out;
    float* ppn1  = points + (size_t)N3 * 10;
    float* ppn2  = ppn1 + (size_t)N1 * 6;
    float* mask1 = ppn2 + (size_t)N2 * 6;
    float* mask2 = mask1 + N1;

    float *y1, *f2m, *y2, *f3m, *z;
    cudaGetSymbolAddress((void**)&y1, g_y1);
    cudaGetSymbolAddress((void**)&f2m, g_f2m);
    cudaGetSymbolAddress((void**)&y2, g_y2);
    cudaGetSymbolAddress((void**)&f3m, g_f3m);
    cudaGetSymbolAddress((void**)&z, g_z);

    // --- Level 1 (coarse, 80ch): CIN chunked 2x40 -> 35.4KB smem ---
    subconv2<80, 80, 128, 4, 20, 4, 40>
        <<<(N1 + 127) / 128, 128, smem_sub(40, 80, 128)>>>(feat1, nbr1, W1, y1, N1);
    score_ppn_mask<80><<<(N1 + 255) / 256, 256>>>(y1, nbr1, W1s, coords1, ppn1, mask1, N1);

    // --- Level 2 (mid, 48ch): single 48 chunk -> 35.9KB smem ---
    apply_att<48><<<(N2 * 12 + 255) / 256, 256>>>(feat2, parent2, mask1, f2m, N2);
    subconv2<48, 48, 128, 4, 12, 4, 48>
        <<<(N2 + 127) / 128, 128, smem_sub(48, 48, 128)>>>(f2m, nbr2, W2, y2, N2);
    score_ppn_mask<48><<<(N2 + 255) / 256, 256>>>(y2, nbr2, W2s, coords2, ppn2, mask2, N2);

    // --- Level 3 (fine, 16ch): 21.6KB smem ---
    apply_att<16><<<(N3 * 4 + 255) / 256, 256>>>(feat3, parent3, mask2, f3m, N3);
    subconv2<16, 16, 256, 8, 4, 4, 16>
        <<<(N3 + 255) / 256, 128, smem_sub(16, 16, 256)>>>(f3m, nbr3, W3, z, N3);
    heads_kernel<<<(N3 + 255) / 256, 256>>>(z, nbr3, W3p, W3s, W3t, points, N3);
}